// round 2
// baseline (speedup 1.0000x reference)
#include <cuda_runtime.h>
#include <math.h>
#include <stdint.h>

// Problem constants
#define BATCH   2
#define S_LEN   2048
#define DM      1024
#define NHEADS  16
#define HDIM    64
#define MROWS   (BATCH * S_LEN)        // 4096
#define PCOLS   (4 * DM)               // 4096
#define ATT_SCALE 0.125f
#define LN_EPS  1e-5f

// Scratch (allocation-free rule: __device__ globals)
__device__ float g_P[(size_t)MROWS * PCOLS];   // silu(x @ W_qkuv): 4096 x 4096
__device__ float g_att[(size_t)MROWS * DM];    // gated attended:   4096 x 1024

// ---------------------------------------------------------------------------
// helpers
// ---------------------------------------------------------------------------
__device__ __forceinline__ unsigned f2tf(float x) {
    unsigned u;
    asm("cvt.rna.tf32.f32 %0, %1;" : "=r"(u) : "f"(x));
    return u;
}
__device__ __forceinline__ float silu_f(float x) {
    return x / (1.0f + __expf(-x));
}
__device__ __forceinline__ void mma_tf32(float c[4], const unsigned a[4], const unsigned b[2]) {
    asm volatile(
        "mma.sync.aligned.m16n8k8.row.col.f32.tf32.tf32.f32 "
        "{%0,%1,%2,%3}, {%4,%5,%6,%7}, {%8,%9}, {%0,%1,%2,%3};\n"
        : "+f"(c[0]), "+f"(c[1]), "+f"(c[2]), "+f"(c[3])
        : "r"(a[0]), "r"(a[1]), "r"(a[2]), "r"(a[3]), "r"(b[0]), "r"(b[1]));
}
__device__ __forceinline__ void cp_async16(uint32_t saddr, const void* gptr) {
    asm volatile("cp.async.cg.shared.global [%0], [%1], 16;\n" :: "r"(saddr), "l"(gptr));
}
__device__ __forceinline__ void cp_commit() {
    asm volatile("cp.async.commit_group;\n");
}
template<int N>
__device__ __forceinline__ void cp_wait() {
    asm volatile("cp.async.wait_group %0;\n" :: "n"(N));
}

// ---------------------------------------------------------------------------
// TF32 GEMM: C[M,N] = (silu?)(A[M,K] @ B[K,N]), row-major fp32.
// CTA tile 128x256x32, 256 threads = 8 warps (2x4), warp tile 64x64.
// 4-stage cp.async pipeline; one __syncthreads per k-step.
// tf32 rounding (cvt.rna) applied in registers after LDS.
// ---------------------------------------------------------------------------
#define G_AS    36          // As row stride (floats)
#define G_BS    264         // Bs row stride (floats)
#define G_AF    (128 * G_AS)            // 4608 floats
#define G_BF    (32 * G_BS)             // 8448 floats
#define G_STG   (G_AF + G_BF)           // 13056 floats / stage
#define G_NSTG  4
#define GEMM_SMEM_BYTES (G_NSTG * G_STG * 4)   // 208896

__global__ void __launch_bounds__(256, 1) gemm_tf32_kernel(
    const float* __restrict__ A, const float* __restrict__ B, float* __restrict__ C,
    int M, int N, int K, int do_silu)
{
    extern __shared__ __align__(16) float sm[];
    const int tid  = threadIdx.x;
    const int warp = tid >> 5, lane = tid & 31;
    const int g = lane >> 2, t = lane & 3;
    const int m0 = blockIdx.y * 128, n0 = blockIdx.x * 256;
    const int wm = (warp >> 2) * 64, wn = (warp & 3) * 64;
    const uint32_t smem_u32 = (uint32_t)__cvta_generic_to_shared(sm);

    const int nk = K >> 5;

    auto load_stage = [&](int ks, int s) {
        const uint32_t as_base = smem_u32 + (uint32_t)(s * G_STG) * 4u;
        const uint32_t bs_base = as_base + (uint32_t)G_AF * 4u;
        const int k0 = ks << 5;
#pragma unroll
        for (int it = 0; it < 4; it++) {            // A: 128x32
            int j = tid + it * 256;
            int r = j >> 3, c4 = (j & 7) * 4;
            cp_async16(as_base + (uint32_t)(r * G_AS + c4) * 4u,
                       A + (size_t)(m0 + r) * K + k0 + c4);
        }
#pragma unroll
        for (int it = 0; it < 8; it++) {            // B: 32x256
            int j = tid + it * 256;
            int r = j >> 6, c4 = (j & 63) * 4;
            cp_async16(bs_base + (uint32_t)(r * G_BS + c4) * 4u,
                       B + (size_t)(k0 + r) * N + n0 + c4);
        }
    };

    float acc[4][8][4];
#pragma unroll
    for (int mt = 0; mt < 4; mt++)
#pragma unroll
        for (int nt = 0; nt < 8; nt++)
#pragma unroll
            for (int i = 0; i < 4; i++) acc[mt][nt][i] = 0.0f;

    // prologue: stages 0..2
#pragma unroll
    for (int s = 0; s < G_NSTG - 1; s++) { load_stage(s, s); cp_commit(); }

    for (int j = 0; j < nk; j++) {
        cp_wait<G_NSTG - 2>();
        __syncthreads();
        if (j + G_NSTG - 1 < nk) {
            load_stage(j + G_NSTG - 1, (j + G_NSTG - 1) & (G_NSTG - 1));
            cp_commit();
        }
        const float* As = sm + (j & (G_NSTG - 1)) * G_STG;
        const float* Bs = As + G_AF;

#pragma unroll
        for (int kk = 0; kk < 4; kk++) {
            const int c = kk * 8 + t;
            unsigned a[4][4], bb[8][2];
#pragma unroll
            for (int mt = 0; mt < 4; mt++) {
                int row = wm + mt * 16 + g;
                a[mt][0] = f2tf(As[row * G_AS + c]);
                a[mt][1] = f2tf(As[(row + 8) * G_AS + c]);
                a[mt][2] = f2tf(As[row * G_AS + c + 4]);
                a[mt][3] = f2tf(As[(row + 8) * G_AS + c + 4]);
            }
#pragma unroll
            for (int nt = 0; nt < 8; nt++) {
                int col = wn + nt * 8 + g;
                bb[nt][0] = f2tf(Bs[c * G_BS + col]);
                bb[nt][1] = f2tf(Bs[(c + 4) * G_BS + col]);
            }
#pragma unroll
            for (int mt = 0; mt < 4; mt++)
#pragma unroll
                for (int nt = 0; nt < 8; nt++)
                    mma_tf32(acc[mt][nt], a[mt], bb[nt]);
        }
    }

    // epilogue
#pragma unroll
    for (int mt = 0; mt < 4; mt++) {
        int row = m0 + wm + mt * 16 + g;
#pragma unroll
        for (int nt = 0; nt < 8; nt++) {
            int col = n0 + wn + nt * 8 + 2 * t;
            float v0 = acc[mt][nt][0], v1 = acc[mt][nt][1];
            float v2 = acc[mt][nt][2], v3 = acc[mt][nt][3];
            if (do_silu) {
                v0 = silu_f(v0); v1 = silu_f(v1); v2 = silu_f(v2); v3 = silu_f(v3);
            }
            *(float2*)(C + (size_t)row * N + col)       = make_float2(v0, v1);
            *(float2*)(C + (size_t)(row + 8) * N + col) = make_float2(v2, v3);
        }
    }
}

// ---------------------------------------------------------------------------
// Fused SiLU-attention + normalizer + LayerNorm(64) + gate.
// Grid: (S/128 q-tiles, B*H). 128 threads = 4 warps, warp owns 32 q rows.
// Double-buffered cp.async K/V; one __syncthreads per key-block.
// S goes accumulator->A-fragment via intra-quad shuffles (no smem round trip).
// ---------------------------------------------------------------------------
#define A_QS    68                      // Q row stride
#define A_KS    68                      // K row stride
#define A_VS    72                      // V row stride (conflict-free B-frags)
#define A_QF    (128 * A_QS)            // 8704 floats
#define A_KF    (64 * A_KS)             // 4352
#define A_VF    (64 * A_VS)             // 4608
#define A_KVSTG (A_KF + A_VF)           // 8960 floats / stage
#define ATT_SMEM_BYTES ((A_QF + 2 * A_KVSTG) * 4)   // 106496

__global__ void __launch_bounds__(128, 2) attn_kernel(
    const float* __restrict__ P, const int* __restrict__ mask,
    const float* __restrict__ gamma, const float* __restrict__ beta,
    float* __restrict__ att)
{
    extern __shared__ __align__(16) float sm[];
    float* Qs = sm;

    const int tid = threadIdx.x, warp = tid >> 5, lane = tid & 31;
    const int g = lane >> 2, t = lane & 3;
    const int bh = blockIdx.y, b = bh >> 4, h = bh & 15;
    const int q0 = blockIdx.x * 128;
    const int wrow = warp * 32;
    const uint32_t smem_u32 = (uint32_t)__cvta_generic_to_shared(sm);

    const float* Pb    = P + (size_t)b * S_LEN * PCOLS;
    const float* qbase = Pb + h * HDIM;
    const float* kbase = Pb + DM + h * HDIM;
    const float* vbase = Pb + 2 * DM + h * HDIM;
    const float* gbase = Pb + 3 * DM + h * HDIM;
    const int*   mbase = mask + (size_t)b * S_LEN * S_LEN;

    auto load_kv = [&](int kb, int s) {
        const uint32_t ks_base = smem_u32 + (uint32_t)(A_QF + s * A_KVSTG) * 4u;
        const uint32_t vs_base = ks_base + (uint32_t)A_KF * 4u;
        const int k0 = kb * 64;
#pragma unroll
        for (int it = 0; it < 8; it++) {
            int j = tid + it * 128;
            int r = j >> 4, c4 = (j & 15) * 4;
            cp_async16(ks_base + (uint32_t)(r * A_KS + c4) * 4u,
                       kbase + (size_t)(k0 + r) * PCOLS + c4);
            cp_async16(vs_base + (uint32_t)(r * A_VS + c4) * 4u,
                       vbase + (size_t)(k0 + r) * PCOLS + c4);
        }
    };

    // Q prologue: load + tf32-round once into smem
#pragma unroll
    for (int it = 0; it < 16; it++) {
        int j = tid + it * 128;
        int r = j >> 4, c4 = (j & 15) * 4;
        float4 v = *(const float4*)(qbase + (size_t)(q0 + r) * PCOLS + c4);
        float4 w;
        w.x = __uint_as_float(f2tf(v.x)); w.y = __uint_as_float(f2tf(v.y));
        w.z = __uint_as_float(f2tf(v.z)); w.w = __uint_as_float(f2tf(v.w));
        *(float4*)&Qs[r * A_QS + c4] = w;
    }

    load_kv(0, 0); cp_commit();

    float o[2][8][4];
#pragma unroll
    for (int mt = 0; mt < 2; mt++)
#pragma unroll
        for (int nt = 0; nt < 8; nt++)
#pragma unroll
            for (int i = 0; i < 4; i++) o[mt][nt][i] = 0.0f;
    int msum[2][2] = {{0, 0}, {0, 0}};

    for (int kb = 0; kb < 32; kb++) {
        cp_wait<0>();
        __syncthreads();   // stage kb visible to all; all warps past stage kb-1
        if (kb + 1 < 32) { load_kv(kb + 1, (kb + 1) & 1); cp_commit(); }

        const float* Ks = sm + A_QF + (kb & 1) * A_KVSTG;
        const float* Vs = Ks + A_KF;

        // ---- S = Q @ K^T (per warp: 32 q-rows x 64 keys) ----
        float s[2][8][4];
#pragma unroll
        for (int mt = 0; mt < 2; mt++)
#pragma unroll
            for (int nt = 0; nt < 8; nt++)
#pragma unroll
                for (int i = 0; i < 4; i++) s[mt][nt][i] = 0.0f;

#pragma unroll
        for (int kk = 0; kk < 8; kk++) {
            const int c = kk * 8 + t;
            unsigned a[2][4];
#pragma unroll
            for (int mt = 0; mt < 2; mt++) {
                int row = wrow + mt * 16 + g;
                a[mt][0] = __float_as_uint(Qs[row * A_QS + c]);
                a[mt][1] = __float_as_uint(Qs[(row + 8) * A_QS + c]);
                a[mt][2] = __float_as_uint(Qs[row * A_QS + c + 4]);
                a[mt][3] = __float_as_uint(Qs[(row + 8) * A_QS + c + 4]);
            }
#pragma unroll
            for (int nt = 0; nt < 8; nt++) {
                unsigned bb[2];
                bb[0] = f2tf(Ks[(nt * 8 + g) * A_KS + c]);
                bb[1] = f2tf(Ks[(nt * 8 + g) * A_KS + c + 4]);
#pragma unroll
                for (int mt = 0; mt < 2; mt++) mma_tf32(s[mt][nt], a[mt], bb);
            }
        }

        // ---- silu * mask, mask row sums, tf32-round in place ----
#pragma unroll
        for (int mt = 0; mt < 2; mt++) {
            const int r0 = q0 + wrow + mt * 16 + g;
#pragma unroll
            for (int nt = 0; nt < 8; nt++) {
                const int* mp = mbase + (size_t)r0 * S_LEN + kb * 64 + nt * 8 + 2 * t;
                int2 m01 = *(const int2*)mp;
                int2 m23 = *(const int2*)(mp + 8 * S_LEN);
                float v0 = silu_f(s[mt][nt][0] * ATT_SCALE) * (float)m01.x;
                float v1 = silu_f(s[mt][nt][1] * ATT_SCALE) * (float)m01.y;
                float v2 = silu_f(s[mt][nt][2] * ATT_SCALE) * (float)m23.x;
                float v3 = silu_f(s[mt][nt][3] * ATT_SCALE) * (float)m23.y;
                msum[mt][0] += m01.x + m01.y;
                msum[mt][1] += m23.x + m23.y;
                s[mt][nt][0] = __uint_as_float(f2tf(v0));
                s[mt][nt][1] = __uint_as_float(f2tf(v1));
                s[mt][nt][2] = __uint_as_float(f2tf(v2));
                s[mt][nt][3] = __uint_as_float(f2tf(v3));
            }
        }

        // ---- O += S @ V, S fragments built via intra-quad shuffles ----
        const int src0 = g * 4 + (t >> 1);
        const int src2 = src0 + 2;
        const bool odd = (t & 1) != 0;
#pragma unroll
        for (int kk = 0; kk < 8; kk++) {
            unsigned a[2][4];
#pragma unroll
            for (int mt = 0; mt < 2; mt++) {
                float e0 = __shfl_sync(0xffffffffu, s[mt][kk][0], src0);
                float e1 = __shfl_sync(0xffffffffu, s[mt][kk][1], src0);
                a[mt][0] = __float_as_uint(odd ? e1 : e0);
                float e2 = __shfl_sync(0xffffffffu, s[mt][kk][2], src0);
                float e3 = __shfl_sync(0xffffffffu, s[mt][kk][3], src0);
                a[mt][1] = __float_as_uint(odd ? e3 : e2);
                float f0 = __shfl_sync(0xffffffffu, s[mt][kk][0], src2);
                float f1 = __shfl_sync(0xffffffffu, s[mt][kk][1], src2);
                a[mt][2] = __float_as_uint(odd ? f1 : f0);
                float f2 = __shfl_sync(0xffffffffu, s[mt][kk][2], src2);
                float f3 = __shfl_sync(0xffffffffu, s[mt][kk][3], src2);
                a[mt][3] = __float_as_uint(odd ? f3 : f2);
            }
            const int c = kk * 8 + t;
#pragma unroll
            for (int nt = 0; nt < 8; nt++) {
                unsigned bb[2];
                bb[0] = f2tf(Vs[c * A_VS + nt * 8 + g]);
                bb[1] = f2tf(Vs[(c + 4) * A_VS + nt * 8 + g]);
#pragma unroll
                for (int mt = 0; mt < 2; mt++) mma_tf32(o[mt][nt], a[mt], bb);
            }
        }
    }

    // ---- normalizer, LayerNorm(64), gate, store ----
    float inv[2][2], mu[2][2], rs[2][2];
#pragma unroll
    for (int mt = 0; mt < 2; mt++) {
#pragma unroll
        for (int hh = 0; hh < 2; hh++) {
            int ms = msum[mt][hh];
            ms += __shfl_xor_sync(0xffffffffu, ms, 1);
            ms += __shfl_xor_sync(0xffffffffu, ms, 2);
            inv[mt][hh] = rsqrtf((float)(ms > 1 ? ms : 1));
        }
        float sum0 = 0.f, sq0 = 0.f, sum1 = 0.f, sq1 = 0.f;
#pragma unroll
        for (int nt = 0; nt < 8; nt++) {
            o[mt][nt][0] *= inv[mt][0]; o[mt][nt][1] *= inv[mt][0];
            o[mt][nt][2] *= inv[mt][1]; o[mt][nt][3] *= inv[mt][1];
            sum0 += o[mt][nt][0] + o[mt][nt][1];
            sq0  += o[mt][nt][0] * o[mt][nt][0] + o[mt][nt][1] * o[mt][nt][1];
            sum1 += o[mt][nt][2] + o[mt][nt][3];
            sq1  += o[mt][nt][2] * o[mt][nt][2] + o[mt][nt][3] * o[mt][nt][3];
        }
        sum0 += __shfl_xor_sync(0xffffffffu, sum0, 1);
        sum0 += __shfl_xor_sync(0xffffffffu, sum0, 2);
        sq0  += __shfl_xor_sync(0xffffffffu, sq0, 1);
        sq0  += __shfl_xor_sync(0xffffffffu, sq0, 2);
        sum1 += __shfl_xor_sync(0xffffffffu, sum1, 1);
        sum1 += __shfl_xor_sync(0xffffffffu, sum1, 2);
        sq1  += __shfl_xor_sync(0xffffffffu, sq1, 1);
        sq1  += __shfl_xor_sync(0xffffffffu, sq1, 2);
        mu[mt][0] = sum0 * (1.0f / 64.0f);
        mu[mt][1] = sum1 * (1.0f / 64.0f);
        rs[mt][0] = rsqrtf(sq0 * (1.0f / 64.0f) - mu[mt][0] * mu[mt][0] + LN_EPS);
        rs[mt][1] = rsqrtf(sq1 * (1.0f / 64.0f) - mu[mt][1] * mu[mt][1] + LN_EPS);
    }

#pragma unroll
    for (int nt = 0; nt < 8; nt++) {
        const int d = nt * 8 + 2 * t;
        const float ga0 = gamma[d], ga1 = gamma[d + 1];
        const float be0 = beta[d],  be1 = beta[d + 1];
#pragma unroll
        for (int mt = 0; mt < 2; mt++) {
            const int r0 = q0 + wrow + mt * 16 + g, r1 = r0 + 8;
            float2 gv0 = *(const float2*)(gbase + (size_t)r0 * PCOLS + d);
            float2 gv1 = *(const float2*)(gbase + (size_t)r1 * PCOLS + d);
            float w0 = ((o[mt][nt][0] - mu[mt][0]) * rs[mt][0] * ga0 + be0) * gv0.x;
            float w1 = ((o[mt][nt][1] - mu[mt][0]) * rs[mt][0] * ga1 + be1) * gv0.y;
            float w2 = ((o[mt][nt][2] - mu[mt][1]) * rs[mt][1] * ga0 + be0) * gv1.x;
            float w3 = ((o[mt][nt][3] - mu[mt][1]) * rs[mt][1] * ga1 + be1) * gv1.y;
            *(float2*)(att + (size_t)(b * S_LEN + r0) * DM + h * HDIM + d) = make_float2(w0, w1);
            *(float2*)(att + (size_t)(b * S_LEN + r1) * DM + h * HDIM + d) = make_float2(w2, w3);
        }
    }
}

// ---------------------------------------------------------------------------
extern "C" void kernel_launch(void* const* d_in, const int* in_sizes, int n_in,
                              void* d_out, int out_size)
{
    const float* tokens = (const float*)d_in[0];
    const int*   mask   = (const int*)d_in[1];
    const float* Wqkuv  = (const float*)d_in[2];
    const float* Wout   = (const float*)d_in[3];
    const float* gamma  = (const float*)d_in[4];
    const float* beta   = (const float*)d_in[5];
    float* out = (float*)d_out;

    float *P = nullptr, *att = nullptr;
    cudaGetSymbolAddress((void**)&P, g_P);
    cudaGetSymbolAddress((void**)&att, g_att);

    cudaFuncSetAttribute(gemm_tf32_kernel, cudaFuncAttributeMaxDynamicSharedMemorySize,
                         GEMM_SMEM_BYTES);
    cudaFuncSetAttribute(attn_kernel, cudaFuncAttributeMaxDynamicSharedMemorySize,
                         ATT_SMEM_BYTES);

    // 1) P = silu(tokens @ W_qkuv)   [4096 x 4096]
    gemm_tf32_kernel<<<dim3(PCOLS / 256, MROWS / 128), 256, GEMM_SMEM_BYTES>>>(
        tokens, Wqkuv, P, MROWS, PCOLS, DM, 1);

    // 2) fused attention + LN + gate -> att [4096 x 1024]
    attn_kernel<<<dim3(S_LEN / 128, BATCH * NHEADS), 128, ATT_SMEM_BYTES>>>(
        P, mask, gamma, beta, att);

    // 3) out = att @ W_out           [4096 x 1024]
    gemm_tf32_kernel<<<dim3(DM / 256, MROWS / 128), 256, GEMM_SMEM_BYTES>>>(
        att, Wout, out, MROWS, DM, DM, 0);
}

// round 4
// speedup vs baseline: 2.1211x; 2.1211x over previous
#include <cuda_runtime.h>
#include <cuda_fp16.h>
#include <math.h>
#include <stdint.h>

// Problem constants
#define BATCH   2
#define S_LEN   2048
#define DM      1024
#define NHEADS  16
#define HDIM    64
#define MROWS   (BATCH * S_LEN)        // 4096
#define PCOLS   (4 * DM)               // 4096
#define ATT_SCALE 0.125f
#define LN_EPS  1e-5f

// Scratch (allocation-free rule: __device__ globals)
__device__ __half g_tok16 [(size_t)MROWS * DM];     // tokens, fp16
__device__ __half g_Wt16  [(size_t)PCOLS * DM];     // W_qkuv^T [4096][1024] fp16 (K-major)
__device__ __half g_Wo16T [(size_t)DM * DM];        // W_out^T  [1024][1024] fp16
__device__ __half g_P16   [(size_t)MROWS * PCOLS];  // silu(x@W), fp16
__device__ __half g_att16 [(size_t)MROWS * DM];     // gated attended, fp16
__device__ __half g_mask16[(size_t)BATCH * S_LEN * S_LEN]; // mask as fp16 0/1
__device__ float  g_inv   [(size_t)BATCH * S_LEN];  // rsqrt(max(rowsum,1))

// ---------------------------------------------------------------------------
// helpers
// ---------------------------------------------------------------------------
__device__ __forceinline__ float fsilu(float x) {
    float e, r;
    asm("ex2.approx.f32 %0, %1;" : "=f"(e) : "f"(-1.4426950408889634f * x));
    asm("rcp.approx.f32 %0, %1;" : "=f"(r) : "f"(1.0f + e));
    return x * r;
}
__device__ __forceinline__ void mma_f16(float c[4], const uint32_t a[4], const uint32_t b[2]) {
    asm volatile(
        "mma.sync.aligned.m16n8k16.row.col.f32.f16.f16.f32 "
        "{%0,%1,%2,%3}, {%4,%5,%6,%7}, {%8,%9}, {%0,%1,%2,%3};\n"
        : "+f"(c[0]), "+f"(c[1]), "+f"(c[2]), "+f"(c[3])
        : "r"(a[0]), "r"(a[1]), "r"(a[2]), "r"(a[3]), "r"(b[0]), "r"(b[1]));
}
__device__ __forceinline__ void cp_async16(uint32_t saddr, const void* gptr) {
    asm volatile("cp.async.cg.shared.global [%0], [%1], 16;\n" :: "r"(saddr), "l"(gptr));
}
__device__ __forceinline__ void cp_commit() { asm volatile("cp.async.commit_group;\n"); }
template<int N>
__device__ __forceinline__ void cp_wait() {
    asm volatile("cp.async.wait_group %0;\n" :: "n"(N));
}
__device__ __forceinline__ uint32_t smem_u32_of(const void* p) {
    uint32_t a;
    asm("{ .reg .u64 tmp; cvta.to.shared.u64 tmp, %1; cvt.u32.u64 %0, tmp; }"
        : "=r"(a) : "l"(p));
    return a;
}
__device__ __forceinline__ uint32_t h2_u32(__half2 h) {
    return *(uint32_t*)&h;
}

// ---------------------------------------------------------------------------
// prep kernels
// ---------------------------------------------------------------------------
__global__ void __launch_bounds__(256) cvt16_kernel(
    const float* __restrict__ in, __half* __restrict__ out, int n)
{
    int i = (blockIdx.x * 256 + threadIdx.x) * 4;
    if (i < n) {
        float4 v = *(const float4*)(in + i);
        *(__half2*)(out + i)     = __floats2half2_rn(v.x, v.y);
        *(__half2*)(out + i + 2) = __floats2half2_rn(v.z, v.w);
    }
}

// Wt16[n*K + k] = fp16(W[k*N + n])
__global__ void __launch_bounds__(256) transpose16_kernel(
    const float* __restrict__ W, __half* __restrict__ Wt, int K, int N)
{
    __shared__ float t[32][33];
    const int n0 = blockIdx.x * 32, k0 = blockIdx.y * 32;
    const int tx = threadIdx.x, ty = threadIdx.y;
#pragma unroll
    for (int i = 0; i < 32; i += 8)
        t[ty + i][tx] = W[(size_t)(k0 + ty + i) * N + n0 + tx];
    __syncthreads();
#pragma unroll
    for (int i = 0; i < 32; i += 8)
        Wt[(size_t)(n0 + ty + i) * K + k0 + tx] = __float2half_rn(t[tx][ty + i]);
}

// mask int32 -> fp16; per-row inv = rsqrt(max(sum,1))
__global__ void __launch_bounds__(256) mask_prep_kernel(
    const int* __restrict__ mask, __half* __restrict__ mask16, float* __restrict__ inv)
{
    const int row = blockIdx.x;
    const int* mr = mask + (size_t)row * S_LEN;
    __half* hr = mask16 + (size_t)row * S_LEN;
    int sum = 0;
    for (int c = threadIdx.x; c < S_LEN; c += 256) {
        int m = mr[c];
        sum += m;
        hr[c] = __int2half_rn(m);
    }
#pragma unroll
    for (int d = 16; d > 0; d >>= 1) sum += __shfl_xor_sync(0xffffffffu, sum, d);
    __shared__ int ws[8];
    if ((threadIdx.x & 31) == 0) ws[threadIdx.x >> 5] = sum;
    __syncthreads();
    if (threadIdx.x == 0) {
        int s = 0;
#pragma unroll
        for (int i = 0; i < 8; i++) s += ws[i];
        inv[row] = rsqrtf(fmaxf((float)s, 1.0f));
    }
}

// ---------------------------------------------------------------------------
// fp16 GEMM: C[M,N] = f(A[M,K] @ Bt[N,K]^T), A,Bt fp16 row-major.
// CTA 128x256x32, 8 warps (2x4), warp 64x64, 4-stage cp.async.
// mode 0: C fp32.  mode 1: C = fp16(silu(.)).
// ---------------------------------------------------------------------------
#define G_AST   40                      // A smem row stride (halves)
#define G_AH    (128 * G_AST)           // 5120 halves
#define G_BH    (256 * G_AST)           // 10240 halves
#define G_STG_H (G_AH + G_BH)           // 15360 halves = 30720 B
#define G_NSTG  4
#define GEMM_SMEM_BYTES (G_NSTG * G_STG_H * 2)   // 122880

__global__ void __launch_bounds__(256) gemm_f16_kernel(
    const __half* __restrict__ A, const __half* __restrict__ Bt, void* __restrict__ Cv,
    int M, int N, int K, int mode)
{
    extern __shared__ __align__(16) __half smh[];
    const int tid  = threadIdx.x;
    const int warp = tid >> 5, lane = tid & 31;
    const int g = lane >> 2, t = lane & 3;
    const int m0 = blockIdx.y * 128, n0 = blockIdx.x * 256;
    const int wm = (warp >> 2) * 64, wn = (warp & 3) * 64;
    const uint32_t smem_u32 = smem_u32_of(smh);
    const int nk = K >> 5;

    auto load_stage = [&](int ks, int s) {
        const uint32_t as_base = smem_u32 + (uint32_t)(s * G_STG_H) * 2u;
        const uint32_t bs_base = as_base + (uint32_t)G_AH * 2u;
        const int k0 = ks << 5;
#pragma unroll
        for (int it = 0; it < 2; it++) {            // A: 128x32 halves
            int idx = tid + it * 256;
            int r = idx >> 2, c8 = (idx & 3) * 8;
            cp_async16(as_base + (uint32_t)(r * G_AST + c8) * 2u,
                       A + (size_t)(m0 + r) * K + k0 + c8);
        }
#pragma unroll
        for (int it = 0; it < 4; it++) {            // B: 256x32 halves
            int idx = tid + it * 256;
            int r = idx >> 2, c8 = (idx & 3) * 8;
            cp_async16(bs_base + (uint32_t)(r * G_AST + c8) * 2u,
                       Bt + (size_t)(n0 + r) * K + k0 + c8);
        }
    };

    float acc[4][8][4];
#pragma unroll
    for (int mt = 0; mt < 4; mt++)
#pragma unroll
        for (int nt = 0; nt < 8; nt++)
#pragma unroll
            for (int i = 0; i < 4; i++) acc[mt][nt][i] = 0.0f;

#pragma unroll
    for (int s = 0; s < G_NSTG - 1; s++) { load_stage(s, s); cp_commit(); }

    for (int j = 0; j < nk; j++) {
        cp_wait<G_NSTG - 2>();
        __syncthreads();
        if (j + G_NSTG - 1 < nk) {
            load_stage(j + G_NSTG - 1, (j + G_NSTG - 1) & (G_NSTG - 1));
            cp_commit();
        }
        const __half* As = smh + (j & (G_NSTG - 1)) * G_STG_H;
        const __half* Bs = As + G_AH;

#pragma unroll
        for (int ks = 0; ks < 2; ks++) {
            uint32_t a[4][4], bb[8][2];
#pragma unroll
            for (int mt = 0; mt < 4; mt++) {
                const int base = (wm + mt * 16 + g) * G_AST + ks * 16 + 2 * t;
                a[mt][0] = *(const uint32_t*)&As[base];
                a[mt][1] = *(const uint32_t*)&As[base + 8 * G_AST];
                a[mt][2] = *(const uint32_t*)&As[base + 8];
                a[mt][3] = *(const uint32_t*)&As[base + 8 * G_AST + 8];
            }
#pragma unroll
            for (int nt = 0; nt < 8; nt++) {
                const int base = (wn + nt * 8 + g) * G_AST + ks * 16 + 2 * t;
                bb[nt][0] = *(const uint32_t*)&Bs[base];
                bb[nt][1] = *(const uint32_t*)&Bs[base + 8];
            }
#pragma unroll
            for (int mt = 0; mt < 4; mt++)
#pragma unroll
                for (int nt = 0; nt < 8; nt++)
                    mma_f16(acc[mt][nt], a[mt], bb[nt]);
        }
    }

    // epilogue
    if (mode == 1) {
        __half* C = (__half*)Cv;
#pragma unroll
        for (int mt = 0; mt < 4; mt++) {
            int row = m0 + wm + mt * 16 + g;
#pragma unroll
            for (int nt = 0; nt < 8; nt++) {
                int col = n0 + wn + nt * 8 + 2 * t;
                *(__half2*)(C + (size_t)row * N + col) =
                    __floats2half2_rn(fsilu(acc[mt][nt][0]), fsilu(acc[mt][nt][1]));
                *(__half2*)(C + (size_t)(row + 8) * N + col) =
                    __floats2half2_rn(fsilu(acc[mt][nt][2]), fsilu(acc[mt][nt][3]));
            }
        }
    } else {
        float* C = (float*)Cv;
#pragma unroll
        for (int mt = 0; mt < 4; mt++) {
            int row = m0 + wm + mt * 16 + g;
#pragma unroll
            for (int nt = 0; nt < 8; nt++) {
                int col = n0 + wn + nt * 8 + 2 * t;
                *(float2*)(C + (size_t)row * N + col) =
                    make_float2(acc[mt][nt][0], acc[mt][nt][1]);
                *(float2*)(C + (size_t)(row + 8) * N + col) =
                    make_float2(acc[mt][nt][2], acc[mt][nt][3]);
            }
        }
    }
}

// ---------------------------------------------------------------------------
// fp16 fused SiLU-attention + normalizer + LayerNorm(64) + gate.
// Grid (S/128, B*H), 256 threads = 8 warps, warp owns 16 q rows.
// S stays in registers (acc layout == A-frag layout); V via ldmatrix.trans.
// One __syncthreads per key-block; K/V double-buffered cp.async.
// ---------------------------------------------------------------------------
#define AT_ST   72                      // row stride (halves)
#define AT_QH   (128 * AT_ST)           // 9216 halves
#define AT_KH   (64 * AT_ST)            // 4608
#define AT_VH   (64 * AT_ST)            // 4608
#define AT_STGH (AT_KH + AT_VH)         // 9216 halves / stage
#define ATT_SMEM_BYTES ((AT_QH + 2 * AT_STGH) * 2)   // 55296

__global__ void __launch_bounds__(256, 2) attn_kernel(
    const __half* __restrict__ P16, const __half* __restrict__ mask16,
    const float* __restrict__ inv_arr,
    const float* __restrict__ gamma, const float* __restrict__ beta,
    __half* __restrict__ att16)
{
    extern __shared__ __align__(16) __half sh[];
    __half* Qs = sh;

    const int tid = threadIdx.x, warp = tid >> 5, lane = tid & 31;
    const int g = lane >> 2, t = lane & 3;
    const int bh = blockIdx.y, b = bh >> 4, h = bh & 15;
    const int q0 = blockIdx.x * 128;
    const uint32_t smem_u32 = smem_u32_of(sh);

    const __half* qb = P16 + (size_t)b * S_LEN * PCOLS + h * HDIM;
    const __half* kb_ = qb + DM;
    const __half* vb_ = qb + 2 * DM;
    const __half* gb_ = qb + 3 * DM;
    const __half* mb_ = mask16 + (size_t)b * S_LEN * S_LEN;

    // Q tile copy (fp16 already)
#pragma unroll
    for (int it = 0; it < 4; it++) {
        int idx = tid + it * 256;
        int r = idx >> 3, c8 = (idx & 7) * 8;
        *(uint4*)&Qs[r * AT_ST + c8] = *(const uint4*)(qb + (size_t)(q0 + r) * PCOLS + c8);
    }

    auto load_kv = [&](int kblk, int s) {
        const uint32_t kbs = smem_u32 + (uint32_t)(AT_QH + s * AT_STGH) * 2u;
        const uint32_t vbs = kbs + (uint32_t)AT_KH * 2u;
        const int k0 = kblk * 64;
#pragma unroll
        for (int it = 0; it < 2; it++) {
            int idx = tid + it * 256;
            int r = idx >> 3, c8 = (idx & 7) * 8;
            cp_async16(kbs + (uint32_t)(r * AT_ST + c8) * 2u,
                       kb_ + (size_t)(k0 + r) * PCOLS + c8);
            cp_async16(vbs + (uint32_t)(r * AT_ST + c8) * 2u,
                       vb_ + (size_t)(k0 + r) * PCOLS + c8);
        }
    };
    load_kv(0, 0); cp_commit();

    float o[8][4];
#pragma unroll
    for (int nt = 0; nt < 8; nt++)
#pragma unroll
        for (int i = 0; i < 4; i++) o[nt][i] = 0.0f;

    const int lrow = warp * 16 + g;

    for (int kb = 0; kb < 32; kb++) {
        cp_wait<0>();
        __syncthreads();
        if (kb + 1 < 32) { load_kv(kb + 1, (kb + 1) & 1); cp_commit(); }

        const __half* Ks = sh + AT_QH + (kb & 1) * AT_STGH;
        const uint32_t v_u32 = smem_u32 + (uint32_t)(AT_QH + (kb & 1) * AT_STGH + AT_KH) * 2u;

        // ---- S = Q @ K^T ----
        float s[8][4];
#pragma unroll
        for (int nt = 0; nt < 8; nt++)
#pragma unroll
            for (int i = 0; i < 4; i++) s[nt][i] = 0.0f;

#pragma unroll
        for (int ks = 0; ks < 4; ks++) {
            uint32_t a[4];
            const int base = lrow * AT_ST + ks * 16 + 2 * t;
            a[0] = *(const uint32_t*)&Qs[base];
            a[1] = *(const uint32_t*)&Qs[base + 8 * AT_ST];
            a[2] = *(const uint32_t*)&Qs[base + 8];
            a[3] = *(const uint32_t*)&Qs[base + 8 * AT_ST + 8];
#pragma unroll
            for (int nt = 0; nt < 8; nt++) {
                const int kbase = (nt * 8 + g) * AT_ST + ks * 16 + 2 * t;
                uint32_t bb[2];
                bb[0] = *(const uint32_t*)&Ks[kbase];
                bb[1] = *(const uint32_t*)&Ks[kbase + 8];
                mma_f16(s[nt], a, bb);
            }
        }

        // ---- silu * mask -> packed fp16 A-frags (registers only) ----
        uint32_t p0[8], p1[8];
#pragma unroll
        for (int nt = 0; nt < 8; nt++) {
            const __half* mp = mb_ + (size_t)(q0 + lrow) * S_LEN + kb * 64 + nt * 8 + 2 * t;
            __half2 m01 = *(const __half2*)mp;
            __half2 m23 = *(const __half2*)(mp + 8 * S_LEN);
            __half2 v01 = __floats2half2_rn(fsilu(s[nt][0] * ATT_SCALE),
                                            fsilu(s[nt][1] * ATT_SCALE));
            __half2 v23 = __floats2half2_rn(fsilu(s[nt][2] * ATT_SCALE),
                                            fsilu(s[nt][3] * ATT_SCALE));
            p0[nt] = h2_u32(__hmul2(v01, m01));
            p1[nt] = h2_u32(__hmul2(v23, m23));
        }

        // ---- O += S @ V  (V B-frags via ldmatrix.trans) ----
        const uint32_t vrow = (uint32_t)(lane & 15);
#pragma unroll
        for (int kk = 0; kk < 4; kk++) {
            uint32_t a[4] = { p0[2 * kk], p1[2 * kk], p0[2 * kk + 1], p1[2 * kk + 1] };
            const uint32_t arow = v_u32 + (uint32_t)((16 * kk + vrow) * AT_ST) * 2u;
#pragma unroll
            for (int nt = 0; nt < 8; nt++) {
                uint32_t b0, b1;
                asm volatile(
                    "ldmatrix.sync.aligned.m8n8.x2.trans.shared.b16 {%0,%1}, [%2];"
                    : "=r"(b0), "=r"(b1) : "r"(arow + (uint32_t)(nt * 16)));
                uint32_t bb[2] = { b0, b1 };
                mma_f16(o[nt], a, bb);
            }
        }
    }

    // ---- normalizer + LayerNorm(64) + gate + store ----
    const float inv0 = inv_arr[b * S_LEN + q0 + lrow];
    const float inv1 = inv_arr[b * S_LEN + q0 + lrow + 8];

    float sum0 = 0.f, sq0 = 0.f, sum1 = 0.f, sq1 = 0.f;
#pragma unroll
    for (int nt = 0; nt < 8; nt++) {
        o[nt][0] *= inv0; o[nt][1] *= inv0;
        o[nt][2] *= inv1; o[nt][3] *= inv1;
        sum0 += o[nt][0] + o[nt][1];
        sq0  += o[nt][0] * o[nt][0] + o[nt][1] * o[nt][1];
        sum1 += o[nt][2] + o[nt][3];
        sq1  += o[nt][2] * o[nt][2] + o[nt][3] * o[nt][3];
    }
    sum0 += __shfl_xor_sync(0xffffffffu, sum0, 1);
    sum0 += __shfl_xor_sync(0xffffffffu, sum0, 2);
    sq0  += __shfl_xor_sync(0xffffffffu, sq0, 1);
    sq0  += __shfl_xor_sync(0xffffffffu, sq0, 2);
    sum1 += __shfl_xor_sync(0xffffffffu, sum1, 1);
    sum1 += __shfl_xor_sync(0xffffffffu, sum1, 2);
    sq1  += __shfl_xor_sync(0xffffffffu, sq1, 1);
    sq1  += __shfl_xor_sync(0xffffffffu, sq1, 2);

    const float mu0 = sum0 * (1.0f / 64.0f);
    const float mu1 = sum1 * (1.0f / 64.0f);
    const float rs0 = rsqrtf(sq0 * (1.0f / 64.0f) - mu0 * mu0 + LN_EPS);
    const float rs1 = rsqrtf(sq1 * (1.0f / 64.0f) - mu1 * mu1 + LN_EPS);

    const int grow0 = q0 + lrow, grow1 = grow0 + 8;
#pragma unroll
    for (int nt = 0; nt < 8; nt++) {
        const int d = nt * 8 + 2 * t;
        const float ga0 = gamma[d], ga1 = gamma[d + 1];
        const float be0 = beta[d],  be1 = beta[d + 1];
        float2 gv0 = __half22float2(*(const __half2*)(gb_ + (size_t)grow0 * PCOLS + d));
        float2 gv1 = __half22float2(*(const __half2*)(gb_ + (size_t)grow1 * PCOLS + d));
        float w0 = ((o[nt][0] - mu0) * rs0 * ga0 + be0) * gv0.x;
        float w1 = ((o[nt][1] - mu0) * rs0 * ga1 + be1) * gv0.y;
        float w2 = ((o[nt][2] - mu1) * rs1 * ga0 + be0) * gv1.x;
        float w3 = ((o[nt][3] - mu1) * rs1 * ga1 + be1) * gv1.y;
        *(__half2*)(att16 + (size_t)(b * S_LEN + grow0) * DM + h * HDIM + d) =
            __floats2half2_rn(w0, w1);
        *(__half2*)(att16 + (size_t)(b * S_LEN + grow1) * DM + h * HDIM + d) =
            __floats2half2_rn(w2, w3);
    }
}

// ---------------------------------------------------------------------------
extern "C" void kernel_launch(void* const* d_in, const int* in_sizes, int n_in,
                              void* d_out, int out_size)
{
    const float* tokens = (const float*)d_in[0];
    const int*   mask   = (const int*)d_in[1];
    const float* Wqkuv  = (const float*)d_in[2];
    const float* Wout   = (const float*)d_in[3];
    const float* gamma  = (const float*)d_in[4];
    const float* beta   = (const float*)d_in[5];
    float* out = (float*)d_out;

    __half *tok16, *Wt16, *Wo16T, *P16, *att16, *mask16;
    float* inv;
    cudaGetSymbolAddress((void**)&tok16,  g_tok16);
    cudaGetSymbolAddress((void**)&Wt16,   g_Wt16);
    cudaGetSymbolAddress((void**)&Wo16T,  g_Wo16T);
    cudaGetSymbolAddress((void**)&P16,    g_P16);
    cudaGetSymbolAddress((void**)&att16,  g_att16);
    cudaGetSymbolAddress((void**)&mask16, g_mask16);
    cudaGetSymbolAddress((void**)&inv,    g_inv);

    cudaFuncSetAttribute(gemm_f16_kernel, cudaFuncAttributeMaxDynamicSharedMemorySize,
                         GEMM_SMEM_BYTES);
    cudaFuncSetAttribute(attn_kernel, cudaFuncAttributeMaxDynamicSharedMemorySize,
                         ATT_SMEM_BYTES);

    // 0) prep: fp16 conversions, weight transposes, mask fp16 + row normalizers
    cvt16_kernel<<<(MROWS * DM) / 1024, 256>>>(tokens, tok16, MROWS * DM);
    transpose16_kernel<<<dim3(PCOLS / 32, DM / 32), dim3(32, 8)>>>(Wqkuv, Wt16, DM, PCOLS);
    transpose16_kernel<<<dim3(DM / 32, DM / 32), dim3(32, 8)>>>(Wout, Wo16T, DM, DM);
    mask_prep_kernel<<<BATCH * S_LEN, 256>>>(mask, mask16, inv);

    // 1) P = fp16(silu(tokens @ W_qkuv))   [4096 x 4096]
    gemm_f16_kernel<<<dim3(PCOLS / 256, MROWS / 128), 256, GEMM_SMEM_BYTES>>>(
        tok16, Wt16, P16, MROWS, PCOLS, DM, 1);

    // 2) fused attention + LN + gate -> att16 [4096 x 1024]
    attn_kernel<<<dim3(S_LEN / 128, BATCH * NHEADS), 256, ATT_SMEM_BYTES>>>(
        P16, mask16, inv, gamma, beta, att16);

    // 3) out = att @ W_out  [4096 x 1024], fp32 out
    gemm_f16_kernel<<<dim3(DM / 256, MROWS / 128), 256, GEMM_SMEM_BYTES>>>(
        att16, Wo16T, out, MROWS, DM, DM, 0);
}

// round 5
// speedup vs baseline: 2.4185x; 1.1402x over previous
#include <cuda_runtime.h>
#include <cuda_fp16.h>
#include <math.h>
#include <stdint.h>

// Problem constants
#define BATCH   2
#define S_LEN   2048
#define DM      1024
#define NHEADS  16
#define HDIM    64
#define MROWS   (BATCH * S_LEN)        // 4096
#define PCOLS   (4 * DM)               // 4096
#define ATT_SCALE 0.125f
#define LN_EPS  1e-5f

// Scratch (allocation-free rule: __device__ globals)
__device__ __half g_tok16 [(size_t)MROWS * DM];
__device__ __half g_Wt16  [(size_t)PCOLS * DM];     // W_qkuv^T fp16 (K-major)
__device__ __half g_Wo16T [(size_t)DM * DM];        // W_out^T fp16
__device__ __half g_P16   [(size_t)MROWS * PCOLS];  // silu(x@W), fp16
__device__ __half g_att16 [(size_t)MROWS * DM];
__device__ __half g_mask16[(size_t)BATCH * S_LEN * S_LEN];
__device__ float  g_inv   [(size_t)BATCH * S_LEN];  // rsqrt(max(rowsum,1))

// ---------------------------------------------------------------------------
// helpers
// ---------------------------------------------------------------------------
__device__ __forceinline__ float fsilu(float x) {
    float e, r;
    asm("ex2.approx.f32 %0, %1;" : "=f"(e) : "f"(-1.4426950408889634f * x));
    asm("rcp.approx.f32 %0, %1;" : "=f"(r) : "f"(1.0f + e));
    return x * r;
}
__device__ __forceinline__ void mma_f16(float c[4], const uint32_t a[4],
                                        uint32_t b0, uint32_t b1) {
    asm volatile(
        "mma.sync.aligned.m16n8k16.row.col.f32.f16.f16.f32 "
        "{%0,%1,%2,%3}, {%4,%5,%6,%7}, {%8,%9}, {%0,%1,%2,%3};\n"
        : "+f"(c[0]), "+f"(c[1]), "+f"(c[2]), "+f"(c[3])
        : "r"(a[0]), "r"(a[1]), "r"(a[2]), "r"(a[3]), "r"(b0), "r"(b1));
}
__device__ __forceinline__ void ldsm_x4(uint32_t addr, uint32_t r[4]) {
    asm volatile("ldmatrix.sync.aligned.m8n8.x4.shared.b16 {%0,%1,%2,%3}, [%4];"
        : "=r"(r[0]), "=r"(r[1]), "=r"(r[2]), "=r"(r[3]) : "r"(addr));
}
__device__ __forceinline__ void ldsm_x4t(uint32_t addr, uint32_t r[4]) {
    asm volatile("ldmatrix.sync.aligned.m8n8.x4.trans.shared.b16 {%0,%1,%2,%3}, [%4];"
        : "=r"(r[0]), "=r"(r[1]), "=r"(r[2]), "=r"(r[3]) : "r"(addr));
}
__device__ __forceinline__ void cp_async16(uint32_t saddr, const void* gptr) {
    asm volatile("cp.async.cg.shared.global [%0], [%1], 16;\n" :: "r"(saddr), "l"(gptr));
}
__device__ __forceinline__ void cp_commit() { asm volatile("cp.async.commit_group;\n"); }
template<int N>
__device__ __forceinline__ void cp_wait() {
    asm volatile("cp.async.wait_group %0;\n" :: "n"(N));
}
__device__ __forceinline__ uint32_t smem_u32_of(const void* p) {
    uint32_t a;
    asm("{ .reg .u64 tmp; cvta.to.shared.u64 tmp, %1; cvt.u32.u64 %0, tmp; }"
        : "=r"(a) : "l"(p));
    return a;
}
__device__ __forceinline__ uint32_t h2_u32(__half2 h) { return *(uint32_t*)&h; }
__device__ __forceinline__ __half2 u32_h2(uint32_t u) { return *(__half2*)&u; }

// ---------------------------------------------------------------------------
// prep kernels
// ---------------------------------------------------------------------------
__global__ void __launch_bounds__(256) cvt16_kernel(
    const float* __restrict__ in, __half* __restrict__ out, int n)
{
    int i = (blockIdx.x * 256 + threadIdx.x) * 4;
    if (i < n) {
        float4 v = *(const float4*)(in + i);
        *(__half2*)(out + i)     = __floats2half2_rn(v.x, v.y);
        *(__half2*)(out + i + 2) = __floats2half2_rn(v.z, v.w);
    }
}

__global__ void __launch_bounds__(256) transpose16_kernel(
    const float* __restrict__ W, __half* __restrict__ Wt, int K, int N)
{
    __shared__ float t[32][33];
    const int n0 = blockIdx.x * 32, k0 = blockIdx.y * 32;
    const int tx = threadIdx.x, ty = threadIdx.y;
#pragma unroll
    for (int i = 0; i < 32; i += 8)
        t[ty + i][tx] = W[(size_t)(k0 + ty + i) * N + n0 + tx];
    __syncthreads();
#pragma unroll
    for (int i = 0; i < 32; i += 8)
        Wt[(size_t)(n0 + ty + i) * K + k0 + tx] = __float2half_rn(t[tx][ty + i]);
}

// vectorized: int4 x2 in, uint4 (8 halves) out; per-row sum -> inv
__global__ void __launch_bounds__(256) mask_prep_kernel(
    const int* __restrict__ mask, __half* __restrict__ mask16, float* __restrict__ inv)
{
    const int row = blockIdx.x;
    const int tid = threadIdx.x;
    const int4* mr4 = (const int4*)(mask + (size_t)row * S_LEN);
    int4 x = mr4[tid * 2], y = mr4[tid * 2 + 1];
    int sum = x.x + x.y + x.z + x.w + y.x + y.y + y.z + y.w;

    uint4 o;
    o.x = h2_u32(__floats2half2_rn((float)x.x, (float)x.y));
    o.y = h2_u32(__floats2half2_rn((float)x.z, (float)x.w));
    o.z = h2_u32(__floats2half2_rn((float)y.x, (float)y.y));
    o.w = h2_u32(__floats2half2_rn((float)y.z, (float)y.w));
    *(uint4*)(mask16 + (size_t)row * S_LEN + tid * 8) = o;

#pragma unroll
    for (int d = 16; d > 0; d >>= 1) sum += __shfl_xor_sync(0xffffffffu, sum, d);
    __shared__ int ws[8];
    if ((tid & 31) == 0) ws[tid >> 5] = sum;
    __syncthreads();
    if (tid == 0) {
        int s = 0;
#pragma unroll
        for (int i = 0; i < 8; i++) s += ws[i];
        inv[row] = rsqrtf(fmaxf((float)s, 1.0f));
    }
}

// ---------------------------------------------------------------------------
// fp16 GEMM: C[M,N] = f(A[M,K] @ Bt[N,K]^T).
// CTA 128x256x32, 512 threads = 16 warps (4x4), warp tile 32x64.
// 4-stage cp.async; ldmatrix.x4 fragment loads.
// mode 0: C fp32.  mode 1: C = fp16(silu(.)).
// ---------------------------------------------------------------------------
#define G_AST   40                      // smem row stride (halves)
#define G_AH    (128 * G_AST)           // 5120 halves
#define G_BH    (256 * G_AST)           // 10240 halves
#define G_STG_H (G_AH + G_BH)           // 15360 halves / stage
#define G_NSTG  4
#define GEMM_SMEM_BYTES (G_NSTG * G_STG_H * 2)   // 122880

__global__ void __launch_bounds__(512) gemm_f16_kernel(
    const __half* __restrict__ A, const __half* __restrict__ Bt, void* __restrict__ Cv,
    int M, int N, int K, int mode)
{
    extern __shared__ __align__(16) __half smh[];
    const int tid  = threadIdx.x;
    const int warp = tid >> 5, lane = tid & 31;
    const int g = lane >> 2, t = lane & 3;
    const int m0 = blockIdx.y * 128, n0 = blockIdx.x * 256;
    const int wm = (warp >> 2) * 32, wn = (warp & 3) * 64;
    const uint32_t smem_u32 = smem_u32_of(smh);
    const int nk = K >> 5;

    auto load_stage = [&](int ks, int s) {
        const uint32_t as_base = smem_u32 + (uint32_t)(s * G_STG_H) * 2u;
        const uint32_t bs_base = as_base + (uint32_t)G_AH * 2u;
        const int k0 = ks << 5;
        {   // A: 128x32 halves, 512 cp -> 1 per thread
            int r = tid >> 2, c8 = (tid & 3) * 8;
            cp_async16(as_base + (uint32_t)(r * G_AST + c8) * 2u,
                       A + (size_t)(m0 + r) * K + k0 + c8);
        }
#pragma unroll
        for (int it = 0; it < 2; it++) {    // B: 256x32 halves
            int idx = tid + it * 512;
            int r = idx >> 2, c8 = (idx & 3) * 8;
            cp_async16(bs_base + (uint32_t)(r * G_AST + c8) * 2u,
                       Bt + (size_t)(n0 + r) * K + k0 + c8);
        }
    };

    float acc[2][8][4];
#pragma unroll
    for (int mt = 0; mt < 2; mt++)
#pragma unroll
        for (int nt = 0; nt < 8; nt++)
#pragma unroll
            for (int i = 0; i < 4; i++) acc[mt][nt][i] = 0.0f;

#pragma unroll
    for (int s = 0; s < G_NSTG - 1; s++) { load_stage(s, s); cp_commit(); }

    // per-lane ldmatrix address components
    const int a_row_l = lane & 15, a_col_l = (lane >> 4) * 8;
    const int b_row_l = ((lane >> 4) << 3) + (lane & 7);
    const int b_col_l = ((lane >> 3) & 1) * 8;

    for (int j = 0; j < nk; j++) {
        cp_wait<G_NSTG - 2>();
        __syncthreads();
        if (j + G_NSTG - 1 < nk) {
            load_stage(j + G_NSTG - 1, (j + G_NSTG - 1) & (G_NSTG - 1));
            cp_commit();
        }
        const uint32_t as_u32 = smem_u32 + (uint32_t)((j & (G_NSTG - 1)) * G_STG_H) * 2u;
        const uint32_t bs_u32 = as_u32 + (uint32_t)G_AH * 2u;

#pragma unroll
        for (int ks = 0; ks < 2; ks++) {
            uint32_t a[2][4], bb[8][4];
#pragma unroll
            for (int mt = 0; mt < 2; mt++) {
                uint32_t addr = as_u32 +
                    (uint32_t)((wm + mt * 16 + a_row_l) * G_AST + ks * 16 + a_col_l) * 2u;
                ldsm_x4(addr, a[mt]);
            }
#pragma unroll
            for (int jj = 0; jj < 4; jj++) {
                uint32_t addr = bs_u32 +
                    (uint32_t)((wn + jj * 16 + b_row_l) * G_AST + ks * 16 + b_col_l) * 2u;
                uint32_t r4[4];
                ldsm_x4(addr, r4);
                bb[2 * jj][0] = r4[0]; bb[2 * jj][1] = r4[1];
                bb[2 * jj + 1][0] = r4[2]; bb[2 * jj + 1][1] = r4[3];
            }
#pragma unroll
            for (int mt = 0; mt < 2; mt++)
#pragma unroll
                for (int nt = 0; nt < 8; nt++)
                    mma_f16(acc[mt][nt], a[mt], bb[nt][0], bb[nt][1]);
        }
    }

    // epilogue
    if (mode == 1) {
        __half* C = (__half*)Cv;
#pragma unroll
        for (int mt = 0; mt < 2; mt++) {
            int row = m0 + wm + mt * 16 + g;
#pragma unroll
            for (int nt = 0; nt < 8; nt++) {
                int col = n0 + wn + nt * 8 + 2 * t;
                *(__half2*)(C + (size_t)row * N + col) =
                    __floats2half2_rn(fsilu(acc[mt][nt][0]), fsilu(acc[mt][nt][1]));
                *(__half2*)(C + (size_t)(row + 8) * N + col) =
                    __floats2half2_rn(fsilu(acc[mt][nt][2]), fsilu(acc[mt][nt][3]));
            }
        }
    } else {
        float* C = (float*)Cv;
#pragma unroll
        for (int mt = 0; mt < 2; mt++) {
            int row = m0 + wm + mt * 16 + g;
#pragma unroll
            for (int nt = 0; nt < 8; nt++) {
                int col = n0 + wn + nt * 8 + 2 * t;
                *(float2*)(C + (size_t)row * N + col) =
                    make_float2(acc[mt][nt][0], acc[mt][nt][1]);
                *(float2*)(C + (size_t)(row + 8) * N + col) =
                    make_float2(acc[mt][nt][2], acc[mt][nt][3]);
            }
        }
    }
}

// ---------------------------------------------------------------------------
// fp16 fused SiLU-attention + normalizer + LayerNorm(64) + gate.
// Grid (S/128, B*H), 256 threads = 8 warps, warp owns 16 q rows.
// ldmatrix.x4 for Q/K/V frags; mask prefetched before S-mma; S in registers.
// ---------------------------------------------------------------------------
#define AT_ST   72
#define AT_QH   (128 * AT_ST)
#define AT_KH   (64 * AT_ST)
#define AT_VH   (64 * AT_ST)
#define AT_STGH (AT_KH + AT_VH)
#define ATT_SMEM_BYTES ((AT_QH + 2 * AT_STGH) * 2)   // 55296

__global__ void __launch_bounds__(256, 2) attn_kernel(
    const __half* __restrict__ P16, const __half* __restrict__ mask16,
    const float* __restrict__ inv_arr,
    const float* __restrict__ gamma, const float* __restrict__ beta,
    __half* __restrict__ att16)
{
    extern __shared__ __align__(16) __half sh[];
    __half* Qs = sh;

    const int tid = threadIdx.x, warp = tid >> 5, lane = tid & 31;
    const int g = lane >> 2, t = lane & 3;
    const int bh = blockIdx.y, b = bh >> 4, h = bh & 15;
    const int q0 = blockIdx.x * 128;
    const uint32_t smem_u32 = smem_u32_of(sh);

    const __half* qb  = P16 + (size_t)b * S_LEN * PCOLS + h * HDIM;
    const __half* kb_ = qb + DM;
    const __half* vb_ = qb + 2 * DM;
    const __half* gb_ = qb + 3 * DM;
    const __half* mb_ = mask16 + (size_t)b * S_LEN * S_LEN;

#pragma unroll
    for (int it = 0; it < 4; it++) {
        int idx = tid + it * 256;
        int r = idx >> 3, c8 = (idx & 7) * 8;
        *(uint4*)&Qs[r * AT_ST + c8] = *(const uint4*)(qb + (size_t)(q0 + r) * PCOLS + c8);
    }

    auto load_kv = [&](int kblk, int s) {
        const uint32_t kbs = smem_u32 + (uint32_t)(AT_QH + s * AT_STGH) * 2u;
        const uint32_t vbs = kbs + (uint32_t)AT_KH * 2u;
        const int k0 = kblk * 64;
#pragma unroll
        for (int it = 0; it < 2; it++) {
            int idx = tid + it * 256;
            int r = idx >> 3, c8 = (idx & 7) * 8;
            cp_async16(kbs + (uint32_t)(r * AT_ST + c8) * 2u,
                       kb_ + (size_t)(k0 + r) * PCOLS + c8);
            cp_async16(vbs + (uint32_t)(r * AT_ST + c8) * 2u,
                       vb_ + (size_t)(k0 + r) * PCOLS + c8);
        }
    };
    load_kv(0, 0); cp_commit();

    float o[8][4];
#pragma unroll
    for (int nt = 0; nt < 8; nt++)
#pragma unroll
        for (int i = 0; i < 4; i++) o[nt][i] = 0.0f;

    const int lrow = warp * 16 + g;
    // ldmatrix lane address components
    const int a_row_l = lane & 15, a_col_l = (lane >> 4) * 8;
    const int b_row_l = ((lane >> 4) << 3) + (lane & 7);
    const int b_col_l = ((lane >> 3) & 1) * 8;

    for (int kb = 0; kb < 32; kb++) {
        cp_wait<0>();
        __syncthreads();
        if (kb + 1 < 32) { load_kv(kb + 1, (kb + 1) & 1); cp_commit(); }

        const uint32_t k_u32 = smem_u32 + (uint32_t)(AT_QH + (kb & 1) * AT_STGH) * 2u;
        const uint32_t v_u32 = k_u32 + (uint32_t)AT_KH * 2u;

        // ---- prefetch mask (consumed after S-mma; latency hidden) ----
        uint32_t pm0[8], pm1[8];
#pragma unroll
        for (int nt = 0; nt < 8; nt++) {
            const __half* mp = mb_ + (size_t)(q0 + lrow) * S_LEN + kb * 64 + nt * 8 + 2 * t;
            pm0[nt] = *(const uint32_t*)mp;
            pm1[nt] = *(const uint32_t*)(mp + 8 * S_LEN);
        }

        // ---- S = Q @ K^T ----
        float s[8][4];
#pragma unroll
        for (int nt = 0; nt < 8; nt++)
#pragma unroll
            for (int i = 0; i < 4; i++) s[nt][i] = 0.0f;

#pragma unroll
        for (int ks = 0; ks < 4; ks++) {
            uint32_t a[4];
            ldsm_x4(smem_u32 +
                (uint32_t)((warp * 16 + a_row_l) * AT_ST + ks * 16 + a_col_l) * 2u, a);
#pragma unroll
            for (int jj = 0; jj < 4; jj++) {
                uint32_t r4[4];
                ldsm_x4(k_u32 +
                    (uint32_t)((jj * 16 + b_row_l) * AT_ST + ks * 16 + b_col_l) * 2u, r4);
                mma_f16(s[2 * jj],     a, r4[0], r4[1]);
                mma_f16(s[2 * jj + 1], a, r4[2], r4[3]);
            }
        }

        // ---- silu * mask -> packed fp16 A-frags ----
        uint32_t p0[8], p1[8];
#pragma unroll
        for (int nt = 0; nt < 8; nt++) {
            __half2 v01 = __floats2half2_rn(fsilu(s[nt][0] * ATT_SCALE),
                                            fsilu(s[nt][1] * ATT_SCALE));
            __half2 v23 = __floats2half2_rn(fsilu(s[nt][2] * ATT_SCALE),
                                            fsilu(s[nt][3] * ATT_SCALE));
            p0[nt] = h2_u32(__hmul2(v01, u32_h2(pm0[nt])));
            p1[nt] = h2_u32(__hmul2(v23, u32_h2(pm1[nt])));
        }

        // ---- O += S @ V  (V frags via ldmatrix.x4.trans) ----
#pragma unroll
        for (int kk = 0; kk < 4; kk++) {
            uint32_t a[4] = { p0[2 * kk], p1[2 * kk], p0[2 * kk + 1], p1[2 * kk + 1] };
#pragma unroll
            for (int jj = 0; jj < 4; jj++) {
                uint32_t r4[4];
                ldsm_x4t(v_u32 +
                    (uint32_t)((16 * kk + a_row_l) * AT_ST + jj * 16 + a_col_l) * 2u, r4);
                mma_f16(o[2 * jj],     a, r4[0], r4[1]);
                mma_f16(o[2 * jj + 1], a, r4[2], r4[3]);
            }
        }
    }

    // ---- normalizer + LayerNorm(64) + gate + store ----
    const float inv0 = inv_arr[b * S_LEN + q0 + lrow];
    const float inv1 = inv_arr[b * S_LEN + q0 + lrow + 8];

    float sum0 = 0.f, sq0 = 0.f, sum1 = 0.f, sq1 = 0.f;
#pragma unroll
    for (int nt = 0; nt < 8; nt++) {
        o[nt][0] *= inv0; o[nt][1] *= inv0;
        o[nt][2] *= inv1; o[nt][3] *= inv1;
        sum0 += o[nt][0] + o[nt][1];
        sq0  += o[nt][0] * o[nt][0] + o[nt][1] * o[nt][1];
        sum1 += o[nt][2] + o[nt][3];
        sq1  += o[nt][2] * o[nt][2] + o[nt][3] * o[nt][3];
    }
    sum0 += __shfl_xor_sync(0xffffffffu, sum0, 1);
    sum0 += __shfl_xor_sync(0xffffffffu, sum0, 2);
    sq0  += __shfl_xor_sync(0xffffffffu, sq0, 1);
    sq0  += __shfl_xor_sync(0xffffffffu, sq0, 2);
    sum1 += __shfl_xor_sync(0xffffffffu, sum1, 1);
    sum1 += __shfl_xor_sync(0xffffffffu, sum1, 2);
    sq1  += __shfl_xor_sync(0xffffffffu, sq1, 1);
    sq1  += __shfl_xor_sync(0xffffffffu, sq1, 2);

    const float mu0 = sum0 * (1.0f / 64.0f);
    const float mu1 = sum1 * (1.0f / 64.0f);
    const float rs0 = rsqrtf(sq0 * (1.0f / 64.0f) - mu0 * mu0 + LN_EPS);
    const float rs1 = rsqrtf(sq1 * (1.0f / 64.0f) - mu1 * mu1 + LN_EPS);

    const int grow0 = q0 + lrow, grow1 = grow0 + 8;
#pragma unroll
    for (int nt = 0; nt < 8; nt++) {
        const int d = nt * 8 + 2 * t;
        const float ga0 = gamma[d], ga1 = gamma[d + 1];
        const float be0 = beta[d],  be1 = beta[d + 1];
        float2 gv0 = __half22float2(*(const __half2*)(gb_ + (size_t)grow0 * PCOLS + d));
        float2 gv1 = __half22float2(*(const __half2*)(gb_ + (size_t)grow1 * PCOLS + d));
        float w0 = ((o[nt][0] - mu0) * rs0 * ga0 + be0) * gv0.x;
        float w1 = ((o[nt][1] - mu0) * rs0 * ga1 + be1) * gv0.y;
        float w2 = ((o[nt][2] - mu1) * rs1 * ga0 + be0) * gv1.x;
        float w3 = ((o[nt][3] - mu1) * rs1 * ga1 + be1) * gv1.y;
        *(__half2*)(att16 + (size_t)(b * S_LEN + grow0) * DM + h * HDIM + d) =
            __floats2half2_rn(w0, w1);
        *(__half2*)(att16 + (size_t)(b * S_LEN + grow1) * DM + h * HDIM + d) =
            __floats2half2_rn(w2, w3);
    }
}

// ---------------------------------------------------------------------------
extern "C" void kernel_launch(void* const* d_in, const int* in_sizes, int n_in,
                              void* d_out, int out_size)
{
    const float* tokens = (const float*)d_in[0];
    const int*   mask   = (const int*)d_in[1];
    const float* Wqkuv  = (const float*)d_in[2];
    const float* Wout   = (const float*)d_in[3];
    const float* gamma  = (const float*)d_in[4];
    const float* beta   = (const float*)d_in[5];
    float* out = (float*)d_out;

    __half *tok16, *Wt16, *Wo16T, *P16, *att16, *mask16;
    float* inv;
    cudaGetSymbolAddress((void**)&tok16,  g_tok16);
    cudaGetSymbolAddress((void**)&Wt16,   g_Wt16);
    cudaGetSymbolAddress((void**)&Wo16T,  g_Wo16T);
    cudaGetSymbolAddress((void**)&P16,    g_P16);
    cudaGetSymbolAddress((void**)&att16,  g_att16);
    cudaGetSymbolAddress((void**)&mask16, g_mask16);
    cudaGetSymbolAddress((void**)&inv,    g_inv);

    cudaFuncSetAttribute(gemm_f16_kernel, cudaFuncAttributeMaxDynamicSharedMemorySize,
                         GEMM_SMEM_BYTES);
    cudaFuncSetAttribute(attn_kernel, cudaFuncAttributeMaxDynamicSharedMemorySize,
                         ATT_SMEM_BYTES);

    // 0) prep
    cvt16_kernel<<<(MROWS * DM) / 1024, 256>>>(tokens, tok16, MROWS * DM);
    transpose16_kernel<<<dim3(PCOLS / 32, DM / 32), dim3(32, 8)>>>(Wqkuv, Wt16, DM, PCOLS);
    transpose16_kernel<<<dim3(DM / 32, DM / 32), dim3(32, 8)>>>(Wout, Wo16T, DM, DM);
    mask_prep_kernel<<<BATCH * S_LEN, 256>>>(mask, mask16, inv);

    // 1) P = fp16(silu(tokens @ W_qkuv))
    gemm_f16_kernel<<<dim3(PCOLS / 256, MROWS / 128), 512, GEMM_SMEM_BYTES>>>(
        tok16, Wt16, P16, MROWS, PCOLS, DM, 1);

    // 2) fused attention + LN + gate
    attn_kernel<<<dim3(S_LEN / 128, BATCH * NHEADS), 256, ATT_SMEM_BYTES>>>(
        P16, mask16, inv, gamma, beta, att16);

    // 3) out = att @ W_out (fp32 out)
    gemm_f16_kernel<<<dim3(DM / 256, MROWS / 128), 512, GEMM_SMEM_BYTES>>>(
        att16, Wo16T, out, MROWS, DM, DM, 0);
}